// round 10
// baseline (speedup 1.0000x reference)
#include <cuda_runtime.h>
#include <cuda_bf16.h>
#include <math.h>
#include <cstdint>
#include <mma.h>

using namespace nvcuda;

#define BB 4
#define CC 512
#define CQ 64
#define NN 4096

// Scratch (device globals; no runtime allocation allowed)
__device__ float g_Q[(size_t)BB * NN * CQ];           // [B][N][Cq]
__device__ float g_K[(size_t)BB * CQ * NN];           // [B][Cq][N]
__device__ __nv_bfloat16 g_V[(size_t)BB * CC * NN];   // [B][C][N] bf16

__device__ __forceinline__ uint32_t smem_u32(const void* p) {
    uint32_t a;
    asm("{ .reg .u64 t; cvta.to.shared.u64 t, %1; cvt.u32.u64 %0, t; }"
        : "=r"(a) : "l"(p));
    return a;
}
#define CP_ASYNC16(dst_u32, src_ptr) \
    asm volatile("cp.async.cg.shared.global [%0], [%1], 16;" \
                 :: "r"(dst_u32), "l"(src_ptr) : "memory")
#define CP_COMMIT() asm volatile("cp.async.commit_group;" ::: "memory")
#define CP_WAIT(n)  asm volatile("cp.async.wait_group %0;" :: "n"(n) : "memory")

// raw tf32 mma m16n8k8 (known fragment layout)
__device__ __forceinline__ void mma_e(float c[4], uint32_t a0, uint32_t a1,
                                      uint32_t a2, uint32_t a3,
                                      uint32_t b0, uint32_t b1) {
    asm volatile(
        "mma.sync.aligned.m16n8k8.row.col.f32.tf32.tf32.f32 "
        "{%0,%1,%2,%3}, {%4,%5,%6,%7}, {%8,%9}, {%0,%1,%2,%3};"
        : "+f"(c[0]), "+f"(c[1]), "+f"(c[2]), "+f"(c[3])
        : "r"(a0), "r"(a1), "r"(a2), "r"(a3), "r"(b0), "r"(b1));
}

#define ASTRIDE 40
#define BSTRIDE 136
#define EPST 132

#define NN_STAGE_FLOATS (128 * ASTRIDE + 32 * BSTRIDE)   // 9472
#define SMEM_NN_BYTES   (2 * NN_STAGE_FLOATS * 4)        // 75776

// ===========================================================================
// V projection (tf32 MMA, bf16 output)
// ===========================================================================
__global__ void __launch_bounds__(256, 2)
vproj_kernel(const float* __restrict__ Wv, const float* __restrict__ X,
             __nv_bfloat16* __restrict__ V) {
    extern __shared__ float sm[];

    const int b  = blockIdx.z;
    const int m0 = blockIdx.y * 128;
    const int n0 = blockIdx.x * 128;
    const float* Ab = Wv + (size_t)m0 * CC;
    const float* Bb = X + (size_t)b * CC * NN + n0;

    const int tid = threadIdx.x;
    const int wid = tid >> 5;
    const int wm = wid >> 1;
    const int wn = wid & 1;

    wmma::fragment<wmma::accumulator, 16, 16, 8, float> acc[2][4];
    #pragma unroll
    for (int f = 0; f < 2; f++)
        #pragma unroll
        for (int g = 0; g < 4; g++)
            wmma::fill_fragment(acc[f][g], 0.0f);

    const uint32_t smb = smem_u32(sm);

    auto issue = [&](int k0, int s) {
        const uint32_t as_u = smb + (uint32_t)(s * NN_STAGE_FLOATS) * 4;
        const uint32_t bs_u = as_u + 128 * ASTRIDE * 4;
        #pragma unroll
        for (int k = 0; k < 4; k++) {
            int t = tid + k * 256;
            int row = t >> 3, seg = t & 7;
            CP_ASYNC16(as_u + (uint32_t)(row * ASTRIDE + seg * 4) * 4,
                       Ab + (size_t)row * CC + k0 + seg * 4);
        }
        #pragma unroll
        for (int k = 0; k < 4; k++) {
            int t = tid + k * 256;
            int row = t >> 5, seg = t & 31;
            CP_ASYNC16(bs_u + (uint32_t)(row * BSTRIDE + seg * 4) * 4,
                       Bb + (size_t)(k0 + row) * NN + seg * 4);
        }
        CP_COMMIT();
    };

    issue(0, 0);

    const int nchunks = CC >> 5;
    for (int c = 0; c < nchunks; c++) {
        const int s = c & 1;
        if (c + 1 < nchunks) { issue((c + 1) << 5, s ^ 1); CP_WAIT(1); }
        else                 { CP_WAIT(0); }
        __syncthreads();

        const float* As = sm + s * NN_STAGE_FLOATS;
        const float* Bs = As + 128 * ASTRIDE;

        #pragma unroll
        for (int kk = 0; kk < 4; kk++) {
            wmma::fragment<wmma::matrix_a, 16, 16, 8, wmma::precision::tf32, wmma::row_major> af[2];
            wmma::fragment<wmma::matrix_b, 16, 16, 8, wmma::precision::tf32, wmma::row_major> bf[4];
            #pragma unroll
            for (int f = 0; f < 2; f++)
                wmma::load_matrix_sync(af[f], As + (wm * 32 + f * 16) * ASTRIDE + kk * 8, ASTRIDE);
            #pragma unroll
            for (int g = 0; g < 4; g++)
                wmma::load_matrix_sync(bf[g], Bs + kk * 8 * BSTRIDE + wn * 64 + g * 16, BSTRIDE);
            #pragma unroll
            for (int f = 0; f < 2; f++)
                #pragma unroll
                for (int g = 0; g < 4; g++)
                    wmma::mma_sync(acc[f][g], af[f], bf[g], acc[f][g]);
        }
        __syncthreads();
    }

    float* Ep = sm;
    #pragma unroll
    for (int f = 0; f < 2; f++)
        #pragma unroll
        for (int g = 0; g < 4; g++)
            wmma::store_matrix_sync(Ep + (wm * 32 + f * 16) * EPST + wn * 64 + g * 16,
                                    acc[f][g], EPST, wmma::mem_row_major);
    __syncthreads();

    __nv_bfloat16* Vb = V + ((size_t)b * CC + m0) * NN + n0;
    #pragma unroll
    for (int t = tid; t < 128 * 32; t += 256) {
        int r = t >> 5, sc = t & 31;
        float4 a = *(const float4*)(Ep + r * EPST + sc * 4);
        __nv_bfloat162 w0 = __float22bfloat162_rn(make_float2(a.x, a.y));
        __nv_bfloat162 w1 = __float22bfloat162_rn(make_float2(a.z, a.w));
        uint2 u = make_uint2(*(uint32_t*)&w0, *(uint32_t*)&w1);
        *(uint2*)(Vb + (size_t)r * NN + sc * 4) = u;
    }
}

// ===========================================================================
// Fused Q+K projection (tf32 MMA)
// ===========================================================================
__global__ void __launch_bounds__(256, 2)
qkproj_kernel(const float* __restrict__ Wq, const float* __restrict__ Wk,
              const float* __restrict__ X,
              float* __restrict__ Q, float* __restrict__ K) {
    extern __shared__ float sm[];

    const int b  = blockIdx.z;
    const int n0 = blockIdx.x * 128;
    const float* Bb = X + (size_t)b * CC * NN + n0;

    const int tid = threadIdx.x;
    const int wid = tid >> 5;
    const int wm = wid >> 1;
    const int wn = wid & 1;

    wmma::fragment<wmma::accumulator, 16, 16, 8, float> acc[2][4];
    #pragma unroll
    for (int f = 0; f < 2; f++)
        #pragma unroll
        for (int g = 0; g < 4; g++)
            wmma::fill_fragment(acc[f][g], 0.0f);

    const uint32_t smb = smem_u32(sm);

    auto issue = [&](int k0, int s) {
        const uint32_t as_u = smb + (uint32_t)(s * NN_STAGE_FLOATS) * 4;
        const uint32_t bs_u = as_u + 128 * ASTRIDE * 4;
        #pragma unroll
        for (int k = 0; k < 4; k++) {
            int t = tid + k * 256;
            int row = t >> 3, seg = t & 7;
            const float* src = (row < 64)
                ? Wq + (size_t)row * CC + k0 + seg * 4
                : Wk + (size_t)(row - 64) * CC + k0 + seg * 4;
            CP_ASYNC16(as_u + (uint32_t)(row * ASTRIDE + seg * 4) * 4, src);
        }
        #pragma unroll
        for (int k = 0; k < 4; k++) {
            int t = tid + k * 256;
            int row = t >> 5, seg = t & 31;
            CP_ASYNC16(bs_u + (uint32_t)(row * BSTRIDE + seg * 4) * 4,
                       Bb + (size_t)(k0 + row) * NN + seg * 4);
        }
        CP_COMMIT();
    };

    issue(0, 0);

    const int nchunks = CC >> 5;
    for (int c = 0; c < nchunks; c++) {
        const int s = c & 1;
        if (c + 1 < nchunks) { issue((c + 1) << 5, s ^ 1); CP_WAIT(1); }
        else                 { CP_WAIT(0); }
        __syncthreads();

        const float* As = sm + s * NN_STAGE_FLOATS;
        const float* Bs = As + 128 * ASTRIDE;

        #pragma unroll
        for (int kk = 0; kk < 4; kk++) {
            wmma::fragment<wmma::matrix_a, 16, 16, 8, wmma::precision::tf32, wmma::row_major> af[2];
            wmma::fragment<wmma::matrix_b, 16, 16, 8, wmma::precision::tf32, wmma::row_major> bf[4];
            #pragma unroll
            for (int f = 0; f < 2; f++)
                wmma::load_matrix_sync(af[f], As + (wm * 32 + f * 16) * ASTRIDE + kk * 8, ASTRIDE);
            #pragma unroll
            for (int g = 0; g < 4; g++)
                wmma::load_matrix_sync(bf[g], Bs + kk * 8 * BSTRIDE + wn * 64 + g * 16, BSTRIDE);
            #pragma unroll
            for (int f = 0; f < 2; f++)
                #pragma unroll
                for (int g = 0; g < 4; g++)
                    wmma::mma_sync(acc[f][g], af[f], bf[g], acc[f][g]);
        }
        __syncthreads();
    }

    float* Ep = sm;
    #pragma unroll
    for (int f = 0; f < 2; f++)
        #pragma unroll
        for (int g = 0; g < 4; g++)
            wmma::store_matrix_sync(Ep + (wm * 32 + f * 16) * EPST + wn * 64 + g * 16,
                                    acc[f][g], EPST, wmma::mem_row_major);
    __syncthreads();

    // K half (rows 64-127): coalesced fp32 row-major stores
    float* Kb = K + (size_t)b * CQ * NN + n0;
    #pragma unroll
    for (int k = 0; k < 8; k++) {
        int t = tid + k * 256;
        int r = t >> 5, sc = t & 31;
        float4 v = *(const float4*)(Ep + (64 + r) * EPST + sc * 4);
        *(float4*)(Kb + (size_t)r * NN + sc * 4) = v;
    }
    // Q half (rows 0-63): transposed stores Q[n][o]
    float* Qb = Q + (size_t)b * NN * CQ;
    #pragma unroll
    for (int k = 0; k < 4; k++) {
        int t = tid + k * 256;
        int r = t & 63, cg = t >> 6;
        #pragma unroll
        for (int c2 = 0; c2 < 8; c2++) {
            int n = cg * 8 + c2;
            Qb[(size_t)(n0 + n) * CQ + r] = Ep[r * EPST + n];
        }
    }
}

// ===========================================================================
// Fused attention kernel: per (batch, i-tile of 64), all 512 channels.
//   Per j-chunk (64): E = Q·K (tf32 raw mma) -> exp -> bf16 P in smem +
//   local row sums; then out-acc += V_chunk · P_chunk (bf16 wmma).
//   Epilogue: out = gamma*acc/l + x. No global P / l, no atomics to gmem.
// ===========================================================================
#define IT   64     // i per block
#define JC   64     // j chunk
#define QST  68     // Q smem stride (floats)  - conflict-free A loads
#define KST  72     // K smem stride (floats)  - conflict-free B loads
#define VST  72     // V smem stride (halves)
#define PST  72     // P smem stride (halves)
#define FEP  72     // epilogue stride (floats)

#define SQ_OFF  0                               // 64*68*4   = 17408
#define SP_OFF  17408                           // 64*72*2   = 9216
#define SL_OFF  26624                           // 64*4      = 256
#define SK_OFF(s) (27648 + (s) * (64 * KST * 4))    // 2x 18432
#define SV_OFF(s) (64512 + (s) * (512 * VST * 2))   // 2x 73728
#define SEP_OFF 27648                           // 512*72*4 = 147456 (aliases K/V)
#define SMEM_FUSED 211968

__global__ void __launch_bounds__(512, 1)
fused_attn_kernel(const float* __restrict__ Q, const float* __restrict__ K,
                  const __nv_bfloat16* __restrict__ V,
                  const float* __restrict__ x, const float* __restrict__ gamma,
                  float* __restrict__ out) {
    extern __shared__ char smc[];
    float* Qs = (float*)(smc + SQ_OFF);
    __nv_bfloat16* Ps = (__nv_bfloat16*)(smc + SP_OFF);
    float* ls = (float*)(smc + SL_OFF);

    const int b  = blockIdx.y;
    const int i0 = blockIdx.x * IT;
    const float* Qg = Q + ((size_t)b * NN + i0) * CQ;
    const float* Kg = K + (size_t)b * CQ * NN;
    const __nv_bfloat16* Vg = V + (size_t)b * CC * NN;

    const int tid = threadIdx.x;
    const int wid = tid >> 5;
    const int lane = tid & 31;
    // E-phase warp coords (4x4 grid of 16x16 tiles)
    const int ei = (wid >> 2) * 16;
    const int ej = (wid & 3) * 16;
    // out-phase warp coords (8c x 2i grid, 64x32 per warp)
    const int wc = (wid >> 1) * 64;
    const int wi = (wid & 1) * 32;

    if (tid < IT) ls[tid] = 0.0f;

    const uint32_t smb = smem_u32(smc);

    auto issue = [&](int c, int s) {
        const uint32_t ku = smb + SK_OFF(s);
        const uint32_t vu = smb + SV_OFF(s);
        const int j0 = c * JC;
        #pragma unroll
        for (int k = 0; k < 2; k++) {              // K: 64 rows x 16 segs
            int t = tid + k * 512;
            int row = t >> 4, seg = t & 15;
            CP_ASYNC16(ku + (uint32_t)(row * KST + seg * 4) * 4,
                       Kg + (size_t)row * NN + j0 + seg * 4);
        }
        #pragma unroll
        for (int k = 0; k < 8; k++) {              // V: 512 rows x 8 segs
            int t = tid + k * 512;
            int row = t >> 3, seg = t & 7;
            CP_ASYNC16(vu + (uint32_t)(row * VST + seg * 8) * 2,
                       Vg + (size_t)row * NN + j0 + seg * 8);
        }
        CP_COMMIT();
    };

    // Q tile load joins group 0
    {
        const uint32_t qu = smb + SQ_OFF;
        #pragma unroll
        for (int k = 0; k < 2; k++) {              // 64 rows x 16 segs
            int t = tid + k * 512;
            int row = t >> 4, seg = t & 15;
            CP_ASYNC16(qu + (uint32_t)(row * QST + seg * 4) * 4,
                       Qg + (size_t)row * CQ + seg * 4);
        }
    }
    issue(0, 0);
    issue(1, 1);

    wmma::fragment<wmma::accumulator, 16, 16, 16, float> acc[4][2];
    #pragma unroll
    for (int f = 0; f < 4; f++)
        #pragma unroll
        for (int g = 0; g < 2; g++)
            wmma::fill_fragment(acc[f][g], 0.0f);

    const int nch = NN / JC;   // 64
    for (int c = 0; c < nch; c++) {
        const int s = c & 1;
        if (c + 1 < nch) { CP_WAIT(1); }
        else             { CP_WAIT(0); }
        __syncthreads();

        // ---- E phase: E[64x64] = Q[64x64] * K[64x64], exp, P bf16, l sums
        {
            const float* Ksf = (float*)(smc + SK_OFF(s));
            float e[8] = {0, 0, 0, 0, 0, 0, 0, 0};
            const int qr = lane >> 2;      // quad row
            const int qc = lane & 3;       // quad col
            #pragma unroll
            for (int kk = 0; kk < 8; kk++) {
                const int o = kk * 8;
                uint32_t a0 = __float_as_uint(Qs[(ei + qr) * QST + o + qc]);
                uint32_t a1 = __float_as_uint(Qs[(ei + qr + 8) * QST + o + qc]);
                uint32_t a2 = __float_as_uint(Qs[(ei + qr) * QST + o + qc + 4]);
                uint32_t a3 = __float_as_uint(Qs[(ei + qr + 8) * QST + o + qc + 4]);
                #pragma unroll
                for (int h = 0; h < 2; h++) {
                    uint32_t b0 = __float_as_uint(Ksf[(o + qc) * KST + ej + h * 8 + qr]);
                    uint32_t b1 = __float_as_uint(Ksf[(o + qc + 4) * KST + ej + h * 8 + qr]);
                    mma_e(e + h * 4, a0, a1, a2, a3, b0, b1);
                }
            }
            #pragma unroll
            for (int q = 0; q < 8; q++) e[q] = __expf(e[q]);

            float slo = (e[0] + e[1]) + (e[4] + e[5]);   // row ei+qr
            float shi = (e[2] + e[3]) + (e[6] + e[7]);   // row ei+qr+8
            slo += __shfl_xor_sync(0xffffffffu, slo, 1);
            slo += __shfl_xor_sync(0xffffffffu, slo, 2);
            shi += __shfl_xor_sync(0xffffffffu, shi, 1);
            shi += __shfl_xor_sync(0xffffffffu, shi, 2);
            if (qc == 0) {
                atomicAdd(ls + ei + qr, slo);
                atomicAdd(ls + ei + qr + 8, shi);
            }

            const int cj = ej + qc * 2;
            __nv_bfloat162 p0 = __float22bfloat162_rn(make_float2(e[0], e[1]));
            __nv_bfloat162 p1 = __float22bfloat162_rn(make_float2(e[2], e[3]));
            __nv_bfloat162 p2 = __float22bfloat162_rn(make_float2(e[4], e[5]));
            __nv_bfloat162 p3 = __float22bfloat162_rn(make_float2(e[6], e[7]));
            *(uint32_t*)(Ps + (ei + qr) * PST + cj)     = *(uint32_t*)&p0;
            *(uint32_t*)(Ps + (ei + qr + 8) * PST + cj) = *(uint32_t*)&p1;
            *(uint32_t*)(Ps + (ei + qr) * PST + cj + 8)     = *(uint32_t*)&p2;
            *(uint32_t*)(Ps + (ei + qr + 8) * PST + cj + 8) = *(uint32_t*)&p3;
        }
        __syncthreads();

        // ---- out phase: acc += V_chunk[512x64] * P[64x64]^T
        {
            const __nv_bfloat16* Vs = (__nv_bfloat16*)(smc + SV_OFF(s));
            #pragma unroll
            for (int kk = 0; kk < 4; kk++) {
                wmma::fragment<wmma::matrix_b, 16, 16, 16, __nv_bfloat16, wmma::col_major> bf[2];
                #pragma unroll
                for (int g = 0; g < 2; g++)
                    wmma::load_matrix_sync(bf[g], Ps + (wi + g * 16) * PST + kk * 16, PST);
                #pragma unroll
                for (int f = 0; f < 4; f++) {
                    wmma::fragment<wmma::matrix_a, 16, 16, 16, __nv_bfloat16, wmma::row_major> af;
                    wmma::load_matrix_sync(af, Vs + (wc + f * 16) * VST + kk * 16, VST);
                    #pragma unroll
                    for (int g = 0; g < 2; g++)
                        wmma::mma_sync(acc[f][g], af, bf[g], acc[f][g]);
                }
            }
        }
        __syncthreads();

        if (c + 2 < nch) issue(c + 2, s);
    }

    // ---- epilogue: out = gamma * acc / l + x
    if (tid < IT) ls[tid] = 1.0f / ls[tid];
    float* Ep = (float*)(smc + SEP_OFF);
    #pragma unroll
    for (int f = 0; f < 4; f++)
        #pragma unroll
        for (int g = 0; g < 2; g++)
            wmma::store_matrix_sync(Ep + (wc + f * 16) * FEP + wi + g * 16,
                                    acc[f][g], FEP, wmma::mem_row_major);
    __syncthreads();

    const float gm = gamma[0];
    #pragma unroll
    for (int it = 0; it < 16; it++) {
        const int row = it * 32 + wid * 2 + (lane >> 4);   // c in 0..511
        const int col = (lane & 15) * 4;                   // i in 0..63
        float4 a = *(const float4*)(Ep + row * FEP + col);
        size_t gi = ((size_t)b * CC + row) * NN + i0 + col;
        float4 xv = *(const float4*)(x + gi);
        float4 o;
        o.x = gm * a.x * ls[col + 0] + xv.x;
        o.y = gm * a.y * ls[col + 1] + xv.y;
        o.z = gm * a.z * ls[col + 2] + xv.z;
        o.w = gm * a.w * ls[col + 3] + xv.w;
        *(float4*)(out + gi) = o;
    }
}

// ---------------------------------------------------------------------------
extern "C" void kernel_launch(void* const* d_in, const int* in_sizes, int n_in,
                              void* d_out, int out_size) {
    const float* x     = (const float*)d_in[0];
    const float* Wq    = (const float*)d_in[1];
    const float* Wk    = (const float*)d_in[2];
    const float* Wv    = (const float*)d_in[3];
    const float* gamma = (const float*)d_in[4];
    float* out = (float*)d_out;

    float *Q, *K;
    __nv_bfloat16 *V;
    cudaGetSymbolAddress((void**)&Q, g_Q);
    cudaGetSymbolAddress((void**)&K, g_K);
    cudaGetSymbolAddress((void**)&V, g_V);

    cudaFuncSetAttribute(vproj_kernel,
                         cudaFuncAttributeMaxDynamicSharedMemorySize, SMEM_NN_BYTES);
    cudaFuncSetAttribute(qkproj_kernel,
                         cudaFuncAttributeMaxDynamicSharedMemorySize, SMEM_NN_BYTES);
    cudaFuncSetAttribute(fused_attn_kernel,
                         cudaFuncAttributeMaxDynamicSharedMemorySize, SMEM_FUSED);

    qkproj_kernel<<<dim3(NN / 128, 1, BB), 256, SMEM_NN_BYTES>>>(Wq, Wk, x, Q, K);

    vproj_kernel<<<dim3(NN / 128, CC / 128, BB), 256, SMEM_NN_BYTES>>>(Wv, x, V);

    fused_attn_kernel<<<dim3(NN / IT, BB), 512, SMEM_FUSED>>>(Q, K, V, x, gamma, out);
}

// round 11
// speedup vs baseline: 1.0979x; 1.0979x over previous
#include <cuda_runtime.h>
#include <cuda_bf16.h>
#include <math.h>
#include <cstdint>
#include <mma.h>

using namespace nvcuda;

#define BB 4
#define CC 512
#define CQ 64
#define NN 4096

// Scratch (device globals; no runtime allocation allowed)
__device__ float g_Q[(size_t)BB * NN * CQ];           // [B][N][Cq]
__device__ float g_K[(size_t)BB * CQ * NN];           // [B][Cq][N]
__device__ __nv_bfloat16 g_V[(size_t)BB * CC * NN];   // [B][C][N] bf16
__device__ __nv_bfloat16 g_P[(size_t)BB * NN * NN];   // [B][N][N] bf16 exp(energy)
__device__ float g_L[(size_t)BB * NN];                // [B][N] row sums

__device__ __forceinline__ uint32_t smem_u32(const void* p) {
    uint32_t a;
    asm("{ .reg .u64 t; cvta.to.shared.u64 t, %1; cvt.u32.u64 %0, t; }"
        : "=r"(a) : "l"(p));
    return a;
}
#define CP_ASYNC16(dst_u32, src_ptr) \
    asm volatile("cp.async.cg.shared.global [%0], [%1], 16;" \
                 :: "r"(dst_u32), "l"(src_ptr) : "memory")
#define CP_COMMIT() asm volatile("cp.async.commit_group;" ::: "memory")
#define CP_WAIT(n)  asm volatile("cp.async.wait_group %0;" :: "n"(n) : "memory")

#define ASTRIDE 40
#define BSTRIDE 136
#define EPST 132

#define NN_STAGE_FLOATS (128 * ASTRIDE + 32 * BSTRIDE)   // 9472
#define SMEM_NN_BYTES   (2 * NN_STAGE_FLOATS * 4)        // 75776

// ===========================================================================
// Fused Q+K projection (tf32 MMA) + L zeroing
// ===========================================================================
__global__ void __launch_bounds__(256, 2)
qkproj_kernel(const float* __restrict__ Wq, const float* __restrict__ Wk,
              const float* __restrict__ X,
              float* __restrict__ Q, float* __restrict__ K,
              float* __restrict__ L) {
    extern __shared__ float sm[];

    const int b  = blockIdx.z;
    const int n0 = blockIdx.x * 128;
    const float* Bb = X + (size_t)b * CC * NN + n0;

    const int tid = threadIdx.x;
    const int wid = tid >> 5;
    const int wm = wid >> 1;
    const int wn = wid & 1;

    // zero this block's L slice (for energy's atomicAdd)
    if (tid < 128) L[(size_t)b * NN + n0 + tid] = 0.0f;

    wmma::fragment<wmma::accumulator, 16, 16, 8, float> acc[2][4];
    #pragma unroll
    for (int f = 0; f < 2; f++)
        #pragma unroll
        for (int g = 0; g < 4; g++)
            wmma::fill_fragment(acc[f][g], 0.0f);

    const uint32_t smb = smem_u32(sm);

    auto issue = [&](int k0, int s) {
        const uint32_t as_u = smb + (uint32_t)(s * NN_STAGE_FLOATS) * 4;
        const uint32_t bs_u = as_u + 128 * ASTRIDE * 4;
        #pragma unroll
        for (int k = 0; k < 4; k++) {
            int t = tid + k * 256;
            int row = t >> 3, seg = t & 7;
            const float* src = (row < 64)
                ? Wq + (size_t)row * CC + k0 + seg * 4
                : Wk + (size_t)(row - 64) * CC + k0 + seg * 4;
            CP_ASYNC16(as_u + (uint32_t)(row * ASTRIDE + seg * 4) * 4, src);
        }
        #pragma unroll
        for (int k = 0; k < 4; k++) {
            int t = tid + k * 256;
            int row = t >> 5, seg = t & 31;
            CP_ASYNC16(bs_u + (uint32_t)(row * BSTRIDE + seg * 4) * 4,
                       Bb + (size_t)(k0 + row) * NN + seg * 4);
        }
        CP_COMMIT();
    };

    issue(0, 0);

    const int nchunks = CC >> 5;   // 16
    for (int c = 0; c < nchunks; c++) {
        const int s = c & 1;
        if (c + 1 < nchunks) { issue((c + 1) << 5, s ^ 1); CP_WAIT(1); }
        else                 { CP_WAIT(0); }
        __syncthreads();

        const float* As = sm + s * NN_STAGE_FLOATS;
        const float* Bs = As + 128 * ASTRIDE;

        #pragma unroll
        for (int kk = 0; kk < 4; kk++) {
            wmma::fragment<wmma::matrix_a, 16, 16, 8, wmma::precision::tf32, wmma::row_major> af[2];
            wmma::fragment<wmma::matrix_b, 16, 16, 8, wmma::precision::tf32, wmma::row_major> bf[4];
            #pragma unroll
            for (int f = 0; f < 2; f++)
                wmma::load_matrix_sync(af[f], As + (wm * 32 + f * 16) * ASTRIDE + kk * 8, ASTRIDE);
            #pragma unroll
            for (int g = 0; g < 4; g++)
                wmma::load_matrix_sync(bf[g], Bs + kk * 8 * BSTRIDE + wn * 64 + g * 16, BSTRIDE);
            #pragma unroll
            for (int f = 0; f < 2; f++)
                #pragma unroll
                for (int g = 0; g < 4; g++)
                    wmma::mma_sync(acc[f][g], af[f], bf[g], acc[f][g]);
        }
        __syncthreads();
    }

    float* Ep = sm;
    #pragma unroll
    for (int f = 0; f < 2; f++)
        #pragma unroll
        for (int g = 0; g < 4; g++)
            wmma::store_matrix_sync(Ep + (wm * 32 + f * 16) * EPST + wn * 64 + g * 16,
                                    acc[f][g], EPST, wmma::mem_row_major);
    __syncthreads();

    // K half (rows 64-127): coalesced fp32 row-major stores
    float* Kb = K + (size_t)b * CQ * NN + n0;
    #pragma unroll
    for (int k = 0; k < 8; k++) {
        int t = tid + k * 256;
        int r = t >> 5, sc = t & 31;
        float4 v = *(const float4*)(Ep + (64 + r) * EPST + sc * 4);
        *(float4*)(Kb + (size_t)r * NN + sc * 4) = v;
    }
    // Q half (rows 0-63): transposed stores Q[n][o]
    float* Qb = Q + (size_t)b * NN * CQ;
    #pragma unroll
    for (int k = 0; k < 4; k++) {
        int t = tid + k * 256;
        int r = t & 63, cg = t >> 6;
        #pragma unroll
        for (int c2 = 0; c2 < 8; c2++) {
            int n = cg * 8 + c2;
            Qb[(size_t)(n0 + n) * CQ + r] = Ep[r * EPST + n];
        }
    }
}

// ===========================================================================
// Heterogeneous kernel: blockIdx.y < 4 -> V projection tile,
//                       blockIdx.y >= 4 -> energy (E=QK, exp, bf16 P, l sums).
// vproj blocks are scheduled first and overlap with energy execution.
// ===========================================================================
__global__ void __launch_bounds__(256, 2)
ev_kernel(const float* __restrict__ Q, const float* __restrict__ K,
          __nv_bfloat16* __restrict__ P, float* __restrict__ l,
          const float* __restrict__ Wv, const float* __restrict__ X,
          __nv_bfloat16* __restrict__ V) {
    extern __shared__ float sm[];

    const int b   = blockIdx.z;
    const int tid = threadIdx.x;
    const int wid = tid >> 5;
    const int lane = tid & 31;
    const int wm = wid >> 1;
    const int wn = wid & 1;
    const uint32_t smb = smem_u32(sm);

    if (blockIdx.y < 4) {
        // ---------------- V projection tile ----------------
        const int m0 = blockIdx.y * 128;
        const int n0 = blockIdx.x * 128;
        const float* Ab = Wv + (size_t)m0 * CC;
        const float* Bb = X + (size_t)b * CC * NN + n0;

        wmma::fragment<wmma::accumulator, 16, 16, 8, float> acc[2][4];
        #pragma unroll
        for (int f = 0; f < 2; f++)
            #pragma unroll
            for (int g = 0; g < 4; g++)
                wmma::fill_fragment(acc[f][g], 0.0f);

        auto issue = [&](int k0, int s) {
            const uint32_t as_u = smb + (uint32_t)(s * NN_STAGE_FLOATS) * 4;
            const uint32_t bs_u = as_u + 128 * ASTRIDE * 4;
            #pragma unroll
            for (int k = 0; k < 4; k++) {
                int t = tid + k * 256;
                int row = t >> 3, seg = t & 7;
                CP_ASYNC16(as_u + (uint32_t)(row * ASTRIDE + seg * 4) * 4,
                           Ab + (size_t)row * CC + k0 + seg * 4);
            }
            #pragma unroll
            for (int k = 0; k < 4; k++) {
                int t = tid + k * 256;
                int row = t >> 5, seg = t & 31;
                CP_ASYNC16(bs_u + (uint32_t)(row * BSTRIDE + seg * 4) * 4,
                           Bb + (size_t)(k0 + row) * NN + seg * 4);
            }
            CP_COMMIT();
        };

        issue(0, 0);
        const int nchunks = CC >> 5;
        for (int c = 0; c < nchunks; c++) {
            const int s = c & 1;
            if (c + 1 < nchunks) { issue((c + 1) << 5, s ^ 1); CP_WAIT(1); }
            else                 { CP_WAIT(0); }
            __syncthreads();

            const float* As = sm + s * NN_STAGE_FLOATS;
            const float* Bs = As + 128 * ASTRIDE;

            #pragma unroll
            for (int kk = 0; kk < 4; kk++) {
                wmma::fragment<wmma::matrix_a, 16, 16, 8, wmma::precision::tf32, wmma::row_major> af[2];
                wmma::fragment<wmma::matrix_b, 16, 16, 8, wmma::precision::tf32, wmma::row_major> bf[4];
                #pragma unroll
                for (int f = 0; f < 2; f++)
                    wmma::load_matrix_sync(af[f], As + (wm * 32 + f * 16) * ASTRIDE + kk * 8, ASTRIDE);
                #pragma unroll
                for (int g = 0; g < 4; g++)
                    wmma::load_matrix_sync(bf[g], Bs + kk * 8 * BSTRIDE + wn * 64 + g * 16, BSTRIDE);
                #pragma unroll
                for (int f = 0; f < 2; f++)
                    #pragma unroll
                    for (int g = 0; g < 4; g++)
                        wmma::mma_sync(acc[f][g], af[f], bf[g], acc[f][g]);
            }
            __syncthreads();
        }

        float* Ep = sm;
        #pragma unroll
        for (int f = 0; f < 2; f++)
            #pragma unroll
            for (int g = 0; g < 4; g++)
                wmma::store_matrix_sync(Ep + (wm * 32 + f * 16) * EPST + wn * 64 + g * 16,
                                        acc[f][g], EPST, wmma::mem_row_major);
        __syncthreads();

        __nv_bfloat16* Vb = V + ((size_t)b * CC + m0) * NN + n0;
        #pragma unroll
        for (int t = tid; t < 128 * 32; t += 256) {
            int r = t >> 5, sc = t & 31;
            float4 a = *(const float4*)(Ep + r * EPST + sc * 4);
            __nv_bfloat162 w0 = __float22bfloat162_rn(make_float2(a.x, a.y));
            __nv_bfloat162 w1 = __float22bfloat162_rn(make_float2(a.z, a.w));
            uint2 u = make_uint2(*(uint32_t*)&w0, *(uint32_t*)&w1);
            *(uint2*)(Vb + (size_t)r * NN + sc * 4) = u;
        }
    } else {
        // ---------------- energy tile ----------------
        const int i0 = (blockIdx.y - 4) * 128;
        const int j0b = blockIdx.x * 128;
        const float* Qb = Q + ((size_t)b * NN + i0) * CQ;
        const float* Kb = K + (size_t)b * CQ * NN + j0b;

        wmma::fragment<wmma::accumulator, 16, 16, 8, float> acc[2][4];
        #pragma unroll
        for (int f = 0; f < 2; f++)
            #pragma unroll
            for (int g = 0; g < 4; g++)
                wmma::fill_fragment(acc[f][g], 0.0f);

        auto issue = [&](int k0, int s) {
            const uint32_t as_u = smb + (uint32_t)(s * NN_STAGE_FLOATS) * 4;
            const uint32_t bs_u = as_u + 128 * ASTRIDE * 4;
            #pragma unroll
            for (int k = 0; k < 4; k++) {
                int t = tid + k * 256;
                int row = t >> 3, seg = t & 7;
                CP_ASYNC16(as_u + (uint32_t)(row * ASTRIDE + seg * 4) * 4,
                           Qb + (size_t)row * CQ + k0 + seg * 4);
            }
            #pragma unroll
            for (int k = 0; k < 4; k++) {
                int t = tid + k * 256;
                int row = t >> 5, seg = t & 31;
                CP_ASYNC16(bs_u + (uint32_t)(row * BSTRIDE + seg * 4) * 4,
                           Kb + (size_t)(k0 + row) * NN + seg * 4);
            }
            CP_COMMIT();
        };

        issue(0, 0);
        #pragma unroll
        for (int c = 0; c < 2; c++) {
            if (c == 0) { issue(32, 1); CP_WAIT(1); }
            else        { CP_WAIT(0); }
            __syncthreads();

            const float* As = sm + c * NN_STAGE_FLOATS;
            const float* Bs = As + 128 * ASTRIDE;

            #pragma unroll
            for (int kk = 0; kk < 4; kk++) {
                wmma::fragment<wmma::matrix_a, 16, 16, 8, wmma::precision::tf32, wmma::row_major> af[2];
                wmma::fragment<wmma::matrix_b, 16, 16, 8, wmma::precision::tf32, wmma::row_major> bf[4];
                #pragma unroll
                for (int f = 0; f < 2; f++)
                    wmma::load_matrix_sync(af[f], As + (wm * 32 + f * 16) * ASTRIDE + kk * 8, ASTRIDE);
                #pragma unroll
                for (int g = 0; g < 4; g++)
                    wmma::load_matrix_sync(bf[g], Bs + kk * 8 * BSTRIDE + wn * 64 + g * 16, BSTRIDE);
                #pragma unroll
                for (int f = 0; f < 2; f++)
                    #pragma unroll
                    for (int g = 0; g < 4; g++)
                        wmma::mma_sync(acc[f][g], af[f], bf[g], acc[f][g]);
            }
            __syncthreads();
        }

        float* Ep = sm;
        #pragma unroll
        for (int f = 0; f < 2; f++)
            #pragma unroll
            for (int g = 0; g < 4; g++) {
                #pragma unroll
                for (int e = 0; e < acc[f][g].num_elements; e++)
                    acc[f][g].x[e] = __expf(acc[f][g].x[e]);
                wmma::store_matrix_sync(Ep + (wm * 32 + f * 16) * EPST + wn * 64 + g * 16,
                                        acc[f][g], EPST, wmma::mem_row_major);
            }
        __syncthreads();

        __nv_bfloat16* Pbase = P + (size_t)b * NN * NN + (size_t)i0 * NN + j0b;
        float* lb = l + (size_t)b * NN + i0;
        #pragma unroll
        for (int k = 0; k < 16; k++) {
            const int r = wid + k * 8;
            float4 v = *(const float4*)(Ep + r * EPST + lane * 4);
            __nv_bfloat162 w0 = __float22bfloat162_rn(make_float2(v.x, v.y));
            __nv_bfloat162 w1 = __float22bfloat162_rn(make_float2(v.z, v.w));
            uint2 u = make_uint2(*(uint32_t*)&w0, *(uint32_t*)&w1);
            *(uint2*)(Pbase + (size_t)r * NN + lane * 4) = u;

            float s = (v.x + v.y) + (v.z + v.w);
            #pragma unroll
            for (int o = 16; o > 0; o >>= 1)
                s += __shfl_xor_sync(0xffffffffu, s, o);
            if (lane == 0)
                atomicAdd(lb + r, s);
        }
    }
}

// ===========================================================================
// Out GEMM (bf16 m16n16k16, NT) + fused normalize/gamma/residual.
// Tile 256(c) x 128(i), 256 threads, 3-stage cp.async.  (R8 version)
// ===========================================================================
#define OT_M 256
#define OT_N 128
#define KC 64
#define HST 72
#define OT_STAGE_HALVES ((OT_M + OT_N) * HST)            // 27648
#define SMEM_OUT_BYTES  (3 * OT_STAGE_HALVES * 2)        // 165888

__global__ void __launch_bounds__(256, 1)
wmma_out_kernel(const __nv_bfloat16* __restrict__ V,
                const __nv_bfloat16* __restrict__ P,
                const float* __restrict__ x, const float* __restrict__ gamma,
                const float* __restrict__ l, float* __restrict__ out) {
    extern __shared__ float smf[];
    __nv_bfloat16* smh = (__nv_bfloat16*)smf;

    const int b  = blockIdx.z;
    const int c0 = blockIdx.x * OT_M;
    const int i0 = blockIdx.y * OT_N;
    const __nv_bfloat16* Vb = V + ((size_t)b * CC + c0) * NN;
    const __nv_bfloat16* Pb = P + ((size_t)b * NN + i0) * NN;

    const int tid = threadIdx.x;
    const int wid = tid >> 5;
    const int wm = wid >> 1;
    const int wn = wid & 1;

    wmma::fragment<wmma::accumulator, 16, 16, 16, float> acc[4][4];
    #pragma unroll
    for (int f = 0; f < 4; f++)
        #pragma unroll
        for (int g = 0; g < 4; g++)
            wmma::fill_fragment(acc[f][g], 0.0f);

    const uint32_t smb = smem_u32(smh);

    auto issue = [&](int j0, int s) {
        const uint32_t as_u = smb + (uint32_t)(s * OT_STAGE_HALVES) * 2;
        const uint32_t bs_u = as_u + OT_M * HST * 2;
        #pragma unroll
        for (int k = 0; k < 8; k++) {
            int t = tid + k * 256;
            int row = t >> 3, seg = t & 7;
            CP_ASYNC16(as_u + (uint32_t)(row * HST + seg * 8) * 2,
                       Vb + (size_t)row * NN + j0 + seg * 8);
        }
        #pragma unroll
        for (int k = 0; k < 4; k++) {
            int t = tid + k * 256;
            int row = t >> 3, seg = t & 7;
            CP_ASYNC16(bs_u + (uint32_t)(row * HST + seg * 8) * 2,
                       Pb + (size_t)row * NN + j0 + seg * 8);
        }
        CP_COMMIT();
    };

    issue(0, 0);
    issue(KC, 1);

    const int nchunks = NN / KC;   // 64
    for (int c = 0; c < nchunks; c++) {
        if (c + 2 < nchunks) { issue((c + 2) * KC, (c + 2) % 3); CP_WAIT(2); }
        else if (c + 1 < nchunks) { CP_WAIT(1); }
        else { CP_WAIT(0); }
        __syncthreads();

        const __nv_bfloat16* As = smh + (c % 3) * OT_STAGE_HALVES;
        const __nv_bfloat16* Bs = As + OT_M * HST;

        #pragma unroll
        for (int kk = 0; kk < KC / 16; kk++) {
            wmma::fragment<wmma::matrix_a, 16, 16, 16, __nv_bfloat16, wmma::row_major> af[4];
            wmma::fragment<wmma::matrix_b, 16, 16, 16, __nv_bfloat16, wmma::col_major> bf[4];
            #pragma unroll
            for (int f = 0; f < 4; f++)
                wmma::load_matrix_sync(af[f], As + (wm * 64 + f * 16) * HST + kk * 16, HST);
            #pragma unroll
            for (int g = 0; g < 4; g++)
                wmma::load_matrix_sync(bf[g], Bs + (wn * 64 + g * 16) * HST + kk * 16, HST);
            #pragma unroll
            for (int f = 0; f < 4; f++)
                #pragma unroll
                for (int g = 0; g < 4; g++)
                    wmma::mma_sync(acc[f][g], af[f], bf[g], acc[f][g]);
        }
        __syncthreads();
    }

    float* Ep = smf;
    float* linv = smf + OT_M * EPST;
    #pragma unroll
    for (int f = 0; f < 4; f++)
        #pragma unroll
        for (int g = 0; g < 4; g++)
            wmma::store_matrix_sync(Ep + (wm * 64 + f * 16) * EPST + wn * 64 + g * 16,
                                    acc[f][g], EPST, wmma::mem_row_major);
    if (tid < 128)
        linv[tid] = 1.0f / l[(size_t)b * NN + i0 + tid];
    __syncthreads();

    const float gm = gamma[0];
    #pragma unroll
    for (int t = tid; t < OT_M * 32; t += 256) {
        int r = t >> 5, sc = t & 31;
        float4 a = *(const float4*)(Ep + r * EPST + sc * 4);
        size_t gi = ((size_t)b * CC + c0 + r) * NN + i0 + sc * 4;
        float4 xv = *(const float4*)(x + gi);
        float4 o;
        o.x = gm * a.x * linv[sc * 4 + 0] + xv.x;
        o.y = gm * a.y * linv[sc * 4 + 1] + xv.y;
        o.z = gm * a.z * linv[sc * 4 + 2] + xv.z;
        o.w = gm * a.w * linv[sc * 4 + 3] + xv.w;
        *(float4*)(out + gi) = o;
    }
}

// ---------------------------------------------------------------------------
extern "C" void kernel_launch(void* const* d_in, const int* in_sizes, int n_in,
                              void* d_out, int out_size) {
    const float* x     = (const float*)d_in[0];
    const float* Wq    = (const float*)d_in[1];
    const float* Wk    = (const float*)d_in[2];
    const float* Wv    = (const float*)d_in[3];
    const float* gamma = (const float*)d_in[4];
    float* out = (float*)d_out;

    float *Q, *K, *L;
    __nv_bfloat16 *V, *P;
    cudaGetSymbolAddress((void**)&Q, g_Q);
    cudaGetSymbolAddress((void**)&K, g_K);
    cudaGetSymbolAddress((void**)&V, g_V);
    cudaGetSymbolAddress((void**)&P, g_P);
    cudaGetSymbolAddress((void**)&L, g_L);

    cudaFuncSetAttribute(qkproj_kernel,
                         cudaFuncAttributeMaxDynamicSharedMemorySize, SMEM_NN_BYTES);
    cudaFuncSetAttribute(ev_kernel,
                         cudaFuncAttributeMaxDynamicSharedMemorySize, SMEM_NN_BYTES);
    cudaFuncSetAttribute(wmma_out_kernel,
                         cudaFuncAttributeMaxDynamicSharedMemorySize, SMEM_OUT_BYTES);

    // Q+K projections + L zeroing
    qkproj_kernel<<<dim3(NN / 128, 1, BB), 256, SMEM_NN_BYTES>>>(Wq, Wk, x, Q, K, L);

    // Heterogeneous launch: y<4 = vproj tiles (first), y>=4 = energy tiles
    ev_kernel<<<dim3(NN / 128, 4 + NN / 128, BB), 256, SMEM_NN_BYTES>>>(
        Q, K, P, L, Wv, x, V);

    // Out GEMM + fused normalize/gamma/residual
    wmma_out_kernel<<<dim3(CC / OT_M, NN / OT_N, BB), 256, SMEM_OUT_BYTES>>>(
        V, P, x, gamma, L, out);
}